// round 2
// baseline (speedup 1.0000x reference)
#include <cuda_runtime.h>
#include <cuda_fp16.h>
#include <math.h>

#define C_CH 256
#define NBIN 49

// Channels-last fp16 scratch for the 4 FPN levels (B=2 fixed by problem).
__device__ __half g_h0[2 * 200 * 200 * C_CH];
__device__ __half g_h1[2 * 100 * 100 * C_CH];
__device__ __half g_h2[2 * 50  * 50  * C_CH];
__device__ __half g_h3[2 * 25  * 25  * C_CH];

// Fused transpose: [B,C,HW] fp32 -> [B,HW,C] fp16, all 4 levels in ONE launch
// so the tiny latency-bound levels overlap with the bandwidth-bound big one.
__global__ void transpose_all(const float* __restrict__ f0,
                              const float* __restrict__ f1,
                              const float* __restrict__ f2,
                              const float* __restrict__ f3,
                              int B) {
    __shared__ float tile[32][33];

    const int HWs[4] = {200 * 200, 100 * 100, 50 * 50, 25 * 25};
    int idx = blockIdx.x;
    int l = 0;
    int nPx = 0;
    #pragma unroll
    for (int q = 0; q < 4; ++q) {
        nPx = (HWs[q] + 31) / 32;
        int nb = nPx * (C_CH / 32) * B;
        if (idx < nb) { l = q; break; }
        idx -= nb;
    }
    int HW = HWs[l];
    const float* in = (l == 0) ? f0 : (l == 1) ? f1 : (l == 2) ? f2 : f3;
    __half* outp    = (l == 0) ? g_h0 : (l == 1) ? g_h1 : (l == 2) ? g_h2 : g_h3;

    int pt = idx % nPx;
    int r  = idx / nPx;
    int cg = r % (C_CH / 32);
    int b  = r / (C_CH / 32);

    int p0 = pt * 32;
    int c0 = cg * 32;
    const float* ib = in   + (size_t)b * C_CH * HW;
    __half*      ob = outp + (size_t)b * C_CH * HW;
    int tx = threadIdx.x, ty = threadIdx.y;

    #pragma unroll
    for (int i = ty; i < 32; i += 8) {
        int p = p0 + tx;
        tile[i][tx] = (p < HW) ? ib[(size_t)(c0 + i) * HW + p] : 0.0f;
    }
    __syncthreads();
    #pragma unroll
    for (int i = ty; i < 32; i += 8) {
        int p = p0 + i;
        if (p < HW) ob[(size_t)p * C_CH + (c0 + tx)] = __float2half_rn(tile[tx][i]);
    }
}

// One 128-thread block per box; thread t owns channels {2t, 2t+1} via half2.
// Every warp tap = 32 lanes x 4B consecutive = one full 128B line.
__global__ __launch_bounds__(128) void roi_main(const float* __restrict__ props,
                                                float* __restrict__ out,
                                                int Np) {
    extern __shared__ float sh[];            // NBIN * 256 fp32 staging
    __shared__ int   s_lo[28], s_hi[28];     // [0..13]=y, [14..27]=x
    __shared__ float s_fr[28], s_va[28];

    int n = blockIdx.x;
    int t = threadIdx.x;

    float bx0 = props[n * 4 + 0];
    float by0 = props[n * 4 + 1];
    float bx1 = props[n * 4 + 2];
    float by1 = props[n * 4 + 3];

    float s  = sqrtf((bx1 - bx0) * (by1 - by0));
    float lv = floorf(4.0f + log2f(s * (1.0f / 224.0f) + 1e-6f));
    lv = fminf(fmaxf(lv, 2.0f), 5.0f);
    int l = (int)lv - 2;

    int H;
    float scale;
    const __half* fp;
    if      (l == 0) { H = 200; scale = 0.25f;    fp = g_h0; }
    else if (l == 1) { H = 100; scale = 0.125f;   fp = g_h1; }
    else if (l == 2) { H = 50;  scale = 0.0625f;  fp = g_h2; }
    else             { H = 25;  scale = 0.03125f; fp = g_h3; }
    int W = H;
    int bidx = n / Np;

    if (t < 28) {
        int  k   = (t < 14) ? t : (t - 14);
        bool isY = (t < 14);
        float off = (float)(k >> 1) + ((float)(k & 1) + 0.5f) * 0.5f;
        float c0  = (isY ? by0 : bx0) * scale;
        float c1  = (isY ? by1 : bx1) * scale;
        float bin = fmaxf(c1 - c0, 1.0f) * (1.0f / 7.0f);
        float c   = c0 + off * bin;
        int   sz  = H;
        float valid = (c >= -1.0f && c <= (float)sz) ? 1.0f : 0.0f;
        float cc  = fmaxf(c, 0.0f);
        int   lo0 = (int)floorf(cc);
        bool  edge = (lo0 >= sz - 1);
        s_lo[t] = edge ? (sz - 1) : lo0;
        s_hi[t] = edge ? (sz - 1) : (lo0 + 1);
        s_fr[t] = edge ? 0.0f : (cc - (float)lo0);
        s_va[t] = valid;
    }
    __syncthreads();

    // half2 base: channels 2t,2t+1. Pixel stride = 128 half2.
    const __half2* fb = (const __half2*)(fp + (size_t)bidx * H * W * C_CH) + t;

    #pragma unroll 1
    for (int by = 0; by < 7; ++by) {
        int   yrow_l[2], yrow_h[2];
        float fy[2], vy[2];
        #pragma unroll
        for (int sy = 0; sy < 2; ++sy) {
            int ky = 2 * by + sy;
            yrow_l[sy] = s_lo[ky] * W;
            yrow_h[sy] = s_hi[ky] * W;
            fy[sy]     = s_fr[ky];
            vy[sy]     = s_va[ky];
        }
        #pragma unroll 1
        for (int bxi = 0; bxi < 7; ++bxi) {
            float a0 = 0.0f, a1 = 0.0f;
            #pragma unroll
            for (int sx = 0; sx < 2; ++sx) {
                int   kx = 14 + 2 * bxi + sx;
                int   xl = s_lo[kx];
                int   xh = s_hi[kx];
                float lx = s_fr[kx];
                float vx = s_va[kx];
                float hx = 1.0f - lx;
                #pragma unroll
                for (int sy = 0; sy < 2; ++sy) {
                    float ly = fy[sy];
                    float hy = 1.0f - ly;
                    float m  = vy[sy] * vx;
                    float2 v00 = __half22float2(fb[(yrow_l[sy] + xl) * (C_CH / 2)]);
                    float2 v01 = __half22float2(fb[(yrow_l[sy] + xh) * (C_CH / 2)]);
                    float2 v10 = __half22float2(fb[(yrow_h[sy] + xl) * (C_CH / 2)]);
                    float2 v11 = __half22float2(fb[(yrow_h[sy] + xh) * (C_CH / 2)]);
                    float w00 = m * hy * hx, w01 = m * hy * lx;
                    float w10 = m * ly * hx, w11 = m * ly * lx;
                    a0 += w00 * v00.x + w01 * v01.x + w10 * v10.x + w11 * v11.x;
                    a1 += w00 * v00.y + w01 * v01.y + w10 * v10.y + w11 * v11.y;
                }
            }
            int bin = by * 7 + bxi;
            sh[(2 * t)     * NBIN + bin] = a0 * 0.25f;
            sh[(2 * t + 1) * NBIN + bin] = a1 * 0.25f;
        }
    }
    __syncthreads();

    // Coalesced float4 write of the whole box tile (matches out[n, c, 7, 7]).
    float4*       o4 = (float4*)(out + (size_t)n * (C_CH * NBIN));
    const float4* s4 = (const float4*)sh;
    #pragma unroll 4
    for (int j = t; j < (C_CH * NBIN) / 4; j += 128) o4[j] = s4[j];
}

extern "C" void kernel_launch(void* const* d_in, const int* in_sizes, int n_in,
                              void* d_out, int out_size) {
    const float* f0    = (const float*)d_in[0];
    const float* f1    = (const float*)d_in[1];
    const float* f2    = (const float*)d_in[2];
    const float* f3    = (const float*)d_in[3];
    const float* props = (const float*)d_in[4];

    int B  = in_sizes[0] / (C_CH * 200 * 200);
    int Np = in_sizes[4] / (4 * B);
    int Nb = B * Np;

    // Total transpose blocks across all 4 levels
    int total = 0;
    const int HWs[4] = {200 * 200, 100 * 100, 50 * 50, 25 * 25};
    for (int l = 0; l < 4; ++l)
        total += ((HWs[l] + 31) / 32) * (C_CH / 32) * B;

    dim3 blk(32, 8);
    transpose_all<<<total, blk>>>(f0, f1, f2, f3, B);

    int smem = NBIN * C_CH * (int)sizeof(float);  // 50176 B
    cudaFuncSetAttribute(roi_main, cudaFuncAttributeMaxDynamicSharedMemorySize, smem);
    roi_main<<<Nb, 128, smem>>>(props, (float*)d_out, Np);
}

// round 3
// speedup vs baseline: 1.4179x; 1.4179x over previous
#include <cuda_runtime.h>
#include <cuda_fp16.h>
#include <math.h>

#define C_CH 256
#define NBIN 49

// Channels-last fp16 scratch for the 4 FPN levels (B=2 fixed by problem).
__device__ __half g_h0[2 * 200 * 200 * C_CH];
__device__ __half g_h1[2 * 100 * 100 * C_CH];
__device__ __half g_h2[2 * 50  * 50  * C_CH];
__device__ __half g_h3[2 * 25  * 25  * C_CH];

// Fused transpose: [B,C,HW] fp32 -> [B,HW,C] fp16, all 4 levels in ONE launch.
// 64ch x 32px tiles: each warp's half2 store is a full 128B line.
__global__ void transpose_all(const float* __restrict__ f0,
                              const float* __restrict__ f1,
                              const float* __restrict__ f2,
                              const float* __restrict__ f3,
                              int B) {
    __shared__ float tile[32][67];   // [px][ch], 67 pad -> conflict-free stores

    const int HWs[4] = {200 * 200, 100 * 100, 50 * 50, 25 * 25};
    int idx = blockIdx.x;
    int l = 0, nPx = 0;
    #pragma unroll
    for (int q = 0; q < 4; ++q) {
        nPx = (HWs[q] + 31) / 32;
        int nb = nPx * (C_CH / 64) * B;
        if (idx < nb) { l = q; break; }
        idx -= nb;
    }
    int HW = HWs[l];
    const float* in = (l == 0) ? f0 : (l == 1) ? f1 : (l == 2) ? f2 : f3;
    __half* outp    = (l == 0) ? g_h0 : (l == 1) ? g_h1 : (l == 2) ? g_h2 : g_h3;

    int pt = idx % nPx;
    int r  = idx / nPx;
    int cg = r % (C_CH / 64);
    int b  = r / (C_CH / 64);

    int p0 = pt * 32;
    int c0 = cg * 64;
    const float* ib = in   + (size_t)b * C_CH * HW;
    __half*      ob = outp + (size_t)b * C_CH * HW;
    int tx = threadIdx.x, ty = threadIdx.y;

    int p = p0 + tx;
    #pragma unroll
    for (int i = ty; i < 64; i += 8)
        tile[tx][i] = (p < HW) ? ib[(size_t)(c0 + i) * HW + p] : 0.0f;
    __syncthreads();
    #pragma unroll
    for (int i = ty; i < 32; i += 8) {
        int pw = p0 + i;
        if (pw < HW) {
            __half2 h = __halves2half2(__float2half_rn(tile[i][2 * tx]),
                                       __float2half_rn(tile[i][2 * tx + 1]));
            ((__half2*)(ob + (size_t)pw * C_CH + c0))[tx] = h;
        }
    }
}

// One block per (box, output-row). 128 threads, thread t = channel pair {2t,2t+1}.
// Tiny static smem (7KB stage) -> high occupancy; 7168 blocks -> ~3 full waves.
__global__ __launch_bounds__(128, 12) void roi_main(const float* __restrict__ props,
                                                    float* __restrict__ out,
                                                    int Np) {
    __shared__ float sh[C_CH * 7];            // [c][bx] stage for this row
    __shared__ int   s_xlo[14], s_xhi[14];
    __shared__ float s_xfr[14], s_xva[14];
    __shared__ int   s_ylo[2],  s_yhi[2];
    __shared__ float s_yfr[2],  s_yva[2];

    int n  = blockIdx.x;
    int by = blockIdx.y;
    int t  = threadIdx.x;

    float bx0 = props[n * 4 + 0];
    float by0 = props[n * 4 + 1];
    float bx1 = props[n * 4 + 2];
    float by1 = props[n * 4 + 3];

    float s  = sqrtf((bx1 - bx0) * (by1 - by0));
    float lv = floorf(4.0f + log2f(s * (1.0f / 224.0f) + 1e-6f));
    lv = fminf(fmaxf(lv, 2.0f), 5.0f);
    int l = (int)lv - 2;

    int H;
    float scale;
    const __half* fp;
    if      (l == 0) { H = 200; scale = 0.25f;    fp = g_h0; }
    else if (l == 1) { H = 100; scale = 0.125f;   fp = g_h1; }
    else if (l == 2) { H = 50;  scale = 0.0625f;  fp = g_h2; }
    else             { H = 25;  scale = 0.03125f; fp = g_h3; }
    int W = H;
    int bidx = n / Np;

    // Sample prep: threads 0..13 -> x samples, threads 14,15 -> y samples of this row.
    if (t < 16) {
        bool isY = (t >= 14);
        int  k   = isY ? (2 * by + (t - 14)) : t;
        float off = (float)(k >> 1) + ((float)(k & 1) + 0.5f) * 0.5f;
        float c0  = (isY ? by0 : bx0) * scale;
        float c1  = (isY ? by1 : bx1) * scale;
        float bin = fmaxf(c1 - c0, 1.0f) * (1.0f / 7.0f);
        float c   = c0 + off * bin;
        float valid = (c >= -1.0f && c <= (float)H) ? 1.0f : 0.0f;
        float cc  = fmaxf(c, 0.0f);
        int   lo0 = (int)floorf(cc);
        bool  edge = (lo0 >= H - 1);
        int lo = edge ? (H - 1) : lo0;
        int hi = edge ? (H - 1) : (lo0 + 1);
        float fr = edge ? 0.0f : (cc - (float)lo0);
        if (isY) { int q = t - 14; s_ylo[q] = lo; s_yhi[q] = hi; s_yfr[q] = fr; s_yva[q] = valid; }
        else     {                 s_xlo[t] = lo; s_xhi[t] = hi; s_xfr[t] = fr; s_xva[t] = valid; }
    }
    __syncthreads();

    const __half2* fb = (const __half2*)(fp + (size_t)bidx * H * W * C_CH) + t;

    int   rl0 = s_ylo[0] * W, rh0 = s_yhi[0] * W;
    int   rl1 = s_ylo[1] * W, rh1 = s_yhi[1] * W;
    float ly0 = s_yfr[0], vy0 = s_yva[0];
    float ly1 = s_yfr[1], vy1 = s_yva[1];
    float hy0 = 1.0f - ly0, hy1 = 1.0f - ly1;

    #pragma unroll 1
    for (int bxi = 0; bxi < 7; ++bxi) {
        float a0 = 0.0f, a1 = 0.0f;
        #pragma unroll
        for (int sx = 0; sx < 2; ++sx) {
            int   kx = 2 * bxi + sx;
            int   xl = s_xlo[kx];
            int   xh = s_xhi[kx];
            float lx = s_xfr[kx];
            float vx = s_xva[kx];
            float hx = 1.0f - lx;
            // y sample 0
            {
                float m = vy0 * vx;
                float2 v00 = __half22float2(fb[(rl0 + xl) * (C_CH / 2)]);
                float2 v01 = __half22float2(fb[(rl0 + xh) * (C_CH / 2)]);
                float2 v10 = __half22float2(fb[(rh0 + xl) * (C_CH / 2)]);
                float2 v11 = __half22float2(fb[(rh0 + xh) * (C_CH / 2)]);
                float w00 = m * hy0 * hx, w01 = m * hy0 * lx;
                float w10 = m * ly0 * hx, w11 = m * ly0 * lx;
                a0 += w00 * v00.x + w01 * v01.x + w10 * v10.x + w11 * v11.x;
                a1 += w00 * v00.y + w01 * v01.y + w10 * v10.y + w11 * v11.y;
            }
            // y sample 1
            {
                float m = vy1 * vx;
                float2 v00 = __half22float2(fb[(rl1 + xl) * (C_CH / 2)]);
                float2 v01 = __half22float2(fb[(rl1 + xh) * (C_CH / 2)]);
                float2 v10 = __half22float2(fb[(rh1 + xl) * (C_CH / 2)]);
                float2 v11 = __half22float2(fb[(rh1 + xh) * (C_CH / 2)]);
                float w00 = m * hy1 * hx, w01 = m * hy1 * lx;
                float w10 = m * ly1 * hx, w11 = m * ly1 * lx;
                a0 += w00 * v00.x + w01 * v01.x + w10 * v10.x + w11 * v11.x;
                a1 += w00 * v00.y + w01 * v01.y + w10 * v10.y + w11 * v11.y;
            }
        }
        sh[(2 * t)     * 7 + bxi] = a0 * 0.25f;
        sh[(2 * t + 1) * 7 + bxi] = a1 * 0.25f;
    }
    __syncthreads();

    // Write this row: out[n, c, by, 0..6] for all c.
    float* orow = out + (size_t)n * (C_CH * NBIN) + by * 7;
    #pragma unroll
    for (int j = t; j < C_CH * 7; j += 128)
        orow[(j / 7) * NBIN + (j % 7)] = sh[j];
}

extern "C" void kernel_launch(void* const* d_in, const int* in_sizes, int n_in,
                              void* d_out, int out_size) {
    const float* f0    = (const float*)d_in[0];
    const float* f1    = (const float*)d_in[1];
    const float* f2    = (const float*)d_in[2];
    const float* f3    = (const float*)d_in[3];
    const float* props = (const float*)d_in[4];

    int B  = in_sizes[0] / (C_CH * 200 * 200);
    int Np = in_sizes[4] / (4 * B);
    int Nb = B * Np;

    int total = 0;
    const int HWs[4] = {200 * 200, 100 * 100, 50 * 50, 25 * 25};
    for (int l = 0; l < 4; ++l)
        total += ((HWs[l] + 31) / 32) * (C_CH / 64) * B;

    dim3 blk(32, 8);
    transpose_all<<<total, blk>>>(f0, f1, f2, f3, B);

    dim3 grd(Nb, 7);
    roi_main<<<grd, 128>>>(props, (float*)d_out, Np);
}

// round 4
// speedup vs baseline: 1.8066x; 1.2741x over previous
#include <cuda_runtime.h>
#include <cuda_fp16.h>
#include <math.h>

#define C_CH 256
#define NBIN 49

// Channels-last fp16 scratch for the 4 FPN levels (B=2 fixed by problem).
__device__ __half g_h0[2 * 200 * 200 * C_CH];
__device__ __half g_h1[2 * 100 * 100 * C_CH];
__device__ __half g_h2[2 * 50  * 50  * C_CH];
__device__ __half g_h3[2 * 25  * 25  * C_CH];

// Fused transpose: [B,C,HW] fp32 -> [B,HW,C] fp16, all 4 levels in ONE launch.
__global__ void transpose_all(const float* __restrict__ f0,
                              const float* __restrict__ f1,
                              const float* __restrict__ f2,
                              const float* __restrict__ f3,
                              int B) {
    __shared__ float tile[32][67];

    const int HWs[4] = {200 * 200, 100 * 100, 50 * 50, 25 * 25};
    int idx = blockIdx.x;
    int l = 0, nPx = 0;
    #pragma unroll
    for (int q = 0; q < 4; ++q) {
        nPx = (HWs[q] + 31) / 32;
        int nb = nPx * (C_CH / 64) * B;
        if (idx < nb) { l = q; break; }
        idx -= nb;
    }
    int HW = HWs[l];
    const float* in = (l == 0) ? f0 : (l == 1) ? f1 : (l == 2) ? f2 : f3;
    __half* outp    = (l == 0) ? g_h0 : (l == 1) ? g_h1 : (l == 2) ? g_h2 : g_h3;

    int pt = idx % nPx;
    int r  = idx / nPx;
    int cg = r % (C_CH / 64);
    int b  = r / (C_CH / 64);

    int p0 = pt * 32;
    int c0 = cg * 64;
    const float* ib = in   + (size_t)b * C_CH * HW;
    __half*      ob = outp + (size_t)b * C_CH * HW;
    int tx = threadIdx.x, ty = threadIdx.y;

    int p = p0 + tx;
    #pragma unroll
    for (int i = ty; i < 64; i += 8)
        tile[tx][i] = (p < HW) ? __ldcs(&ib[(size_t)(c0 + i) * HW + p]) : 0.0f;
    __syncthreads();
    #pragma unroll
    for (int i = ty; i < 32; i += 8) {
        int pw = p0 + i;
        if (pw < HW) {
            __half2 h = __halves2half2(__float2half_rn(tile[i][2 * tx]),
                                       __float2half_rn(tile[i][2 * tx + 1]));
            ((__half2*)(ob + (size_t)pw * C_CH + c0))[tx] = h;
        }
    }
}

// One 64-thread block per (box, output-row). Thread t owns channels {4t..4t+3}
// via one uint2 (= 2x half2) load per tap. All tap offsets/weights precomputed
// once per block into smem as uint4 (LDS.128 in the hot loop). Bilinear combine
// per 2x2-sample group done in HFMA2; fp32 accumulation across groups.
__global__ __launch_bounds__(64, 20) void roi_main(const float* __restrict__ props,
                                                   float* __restrict__ out,
                                                   int Np) {
    __shared__ __align__(16) float stage[7 * 260];   // [bx][c], stride 260
    __shared__ uint4 s_off[28];   // [bxi*4+g] -> 4 tap pixel-offsets (uint2 units)
    __shared__ uint4 s_w[28];     // [bxi*4+g] -> 4 duplicated-half2 weights
    __shared__ int   s_xlo[14], s_xhi[14];
    __shared__ float s_xfr[14], s_xva[14];
    __shared__ int   s_ylo[2],  s_yhi[2];
    __shared__ float s_yfr[2],  s_yva[2];

    int n  = blockIdx.x;
    int by = blockIdx.y;
    int t  = threadIdx.x;

    float bx0 = props[n * 4 + 0];
    float by0 = props[n * 4 + 1];
    float bx1 = props[n * 4 + 2];
    float by1 = props[n * 4 + 3];

    float s  = sqrtf((bx1 - bx0) * (by1 - by0));
    float lv = floorf(4.0f + log2f(s * (1.0f / 224.0f) + 1e-6f));
    lv = fminf(fmaxf(lv, 2.0f), 5.0f);
    int l = (int)lv - 2;

    int H;
    float scale;
    const __half* fp;
    if      (l == 0) { H = 200; scale = 0.25f;    fp = g_h0; }
    else if (l == 1) { H = 100; scale = 0.125f;   fp = g_h1; }
    else if (l == 2) { H = 50;  scale = 0.0625f;  fp = g_h2; }
    else             { H = 25;  scale = 0.03125f; fp = g_h3; }
    int W = H;
    int bidx = n / Np;

    // Sample prep: threads 0..13 -> x samples, 14..15 -> the 2 y samples of this row.
    if (t < 16) {
        bool isY = (t >= 14);
        int  k   = isY ? (2 * by + (t - 14)) : t;
        float off = (float)(k >> 1) + ((float)(k & 1) + 0.5f) * 0.5f;
        float c0  = (isY ? by0 : bx0) * scale;
        float c1  = (isY ? by1 : bx1) * scale;
        float bin = fmaxf(c1 - c0, 1.0f) * (1.0f / 7.0f);
        float c   = c0 + off * bin;
        float valid = (c >= -1.0f && c <= (float)H) ? 1.0f : 0.0f;
        float cc  = fmaxf(c, 0.0f);
        int   lo0 = (int)floorf(cc);
        bool  edge = (lo0 >= H - 1);
        int lo = edge ? (H - 1) : lo0;
        int hi = edge ? (H - 1) : (lo0 + 1);
        float fr = edge ? 0.0f : (cc - (float)lo0);
        if (isY) { int q = t - 14; s_ylo[q] = lo; s_yhi[q] = hi; s_yfr[q] = fr; s_yva[q] = valid; }
        else     {                 s_xlo[t] = lo; s_xhi[t] = hi; s_xfr[t] = fr; s_xva[t] = valid; }
    }
    __syncthreads();

    // Precompute 112 taps: i = bxi*16 + g*4 + tap; g = (sy,sx) group.
    #pragma unroll
    for (int i = t; i < 112; i += 64) {
        int bxi = i >> 4, r = i & 15, g = r >> 2, tap = r & 3;
        int sy = g >> 1, sx = g & 1;
        int kx = 2 * bxi + sx;
        int row = (tap & 2) ? s_yhi[sy] : s_ylo[sy];
        int x   = (tap & 1) ? s_xhi[kx] : s_xlo[kx];
        float wy = (tap & 2) ? s_yfr[sy] : (1.0f - s_yfr[sy]);
        float wx = (tap & 1) ? s_xfr[kx] : (1.0f - s_xfr[kx]);
        float w  = s_yva[sy] * s_xva[kx] * wy * wx;
        ((unsigned*)s_off)[i] = (unsigned)((row * W + x) * (C_CH / 4));
        unsigned hb = (unsigned)__half_as_ushort(__float2half_rn(w));
        ((unsigned*)s_w)[i] = hb | (hb << 16);
    }
    __syncthreads();

    const uint2* fb = (const uint2*)(fp + (size_t)bidx * H * W * C_CH) + t;

    #pragma unroll 1
    for (int bxi = 0; bxi < 7; ++bxi) {
        float r0 = 0.0f, r1 = 0.0f, r2 = 0.0f, r3 = 0.0f;
        #pragma unroll
        for (int g = 0; g < 4; ++g) {
            uint4 off = s_off[bxi * 4 + g];
            uint4 wq  = s_w[bxi * 4 + g];
            uint2 v0 = __ldg(fb + off.x);
            uint2 v1 = __ldg(fb + off.y);
            uint2 v2 = __ldg(fb + off.z);
            uint2 v3 = __ldg(fb + off.w);
            __half2 w0 = *reinterpret_cast<const __half2*>(&wq.x);
            __half2 w1 = *reinterpret_cast<const __half2*>(&wq.y);
            __half2 w2 = *reinterpret_cast<const __half2*>(&wq.z);
            __half2 w3 = *reinterpret_cast<const __half2*>(&wq.w);
            __half2 aL = __hmul2(*reinterpret_cast<const __half2*>(&v0.x), w0);
            __half2 aH = __hmul2(*reinterpret_cast<const __half2*>(&v0.y), w0);
            aL = __hfma2(*reinterpret_cast<const __half2*>(&v1.x), w1, aL);
            aH = __hfma2(*reinterpret_cast<const __half2*>(&v1.y), w1, aH);
            aL = __hfma2(*reinterpret_cast<const __half2*>(&v2.x), w2, aL);
            aH = __hfma2(*reinterpret_cast<const __half2*>(&v2.y), w2, aH);
            aL = __hfma2(*reinterpret_cast<const __half2*>(&v3.x), w3, aL);
            aH = __hfma2(*reinterpret_cast<const __half2*>(&v3.y), w3, aH);
            float2 fL = __half22float2(aL);
            float2 fH = __half22float2(aH);
            r0 += fL.x; r1 += fL.y; r2 += fH.x; r3 += fH.y;
        }
        *reinterpret_cast<float4*>(&stage[bxi * 260 + 4 * t]) =
            make_float4(r0 * 0.25f, r1 * 0.25f, r2 * 0.25f, r3 * 0.25f);
    }
    __syncthreads();

    // Write this row: out[n, c, by, bx] for all c, bx. j = c*7 + bx keeps
    // global writes contiguous across lanes.
    float* orow = out + (size_t)n * (C_CH * NBIN) + by * 7;
    #pragma unroll
    for (int j = t; j < C_CH * 7; j += 64) {
        int c  = j / 7;
        int bx = j - c * 7;
        orow[c * NBIN + bx] = stage[bx * 260 + c];
    }
}

extern "C" void kernel_launch(void* const* d_in, const int* in_sizes, int n_in,
                              void* d_out, int out_size) {
    const float* f0    = (const float*)d_in[0];
    const float* f1    = (const float*)d_in[1];
    const float* f2    = (const float*)d_in[2];
    const float* f3    = (const float*)d_in[3];
    const float* props = (const float*)d_in[4];

    int B  = in_sizes[0] / (C_CH * 200 * 200);
    int Np = in_sizes[4] / (4 * B);
    int Nb = B * Np;

    int total = 0;
    const int HWs[4] = {200 * 200, 100 * 100, 50 * 50, 25 * 25};
    for (int l = 0; l < 4; ++l)
        total += ((HWs[l] + 31) / 32) * (C_CH / 64) * B;

    dim3 blk(32, 8);
    transpose_all<<<total, blk>>>(f0, f1, f2, f3, B);

    dim3 grd(Nb, 7);
    roi_main<<<grd, 64>>>(props, (float*)d_out, Np);
}